// round 1
// baseline (speedup 1.0000x reference)
#include <cuda_runtime.h>

// Problem constants
#define BATCH 8
#define NCLS 19
#define HH 768
#define WW 768
#define HWP (HH * WW)                 // 589824
#define N_PIX (BATCH * HWP)           // 4718592
#define IGNORE_LBL 255
#define MIN_KEPT_K 262144u
#define THRESH_F 0.7f

// Scratch (no cudaMalloc allowed): 18.9 MB
__device__ float g_prob[N_PIX];
__device__ unsigned int g_hist[256];
__device__ unsigned int g_prefix;
__device__ unsigned int g_k;
__device__ unsigned int g_num_valid;
__device__ double g_sum;
__device__ unsigned int g_cnt;

// ---------------------------------------------------------------------------
__global__ void init_kernel() {
    int t = threadIdx.x;
    if (t < 256) g_hist[t] = 0;
    if (t == 0) {
        g_prefix = 0u;
        g_k = MIN_KEPT_K;   // k = min(N, MIN_KEPT) = MIN_KEPT since N > MIN_KEPT
        g_num_valid = 0u;
        g_sum = 0.0;
        g_cnt = 0u;
    }
}

// ---------------------------------------------------------------------------
// Main pass: log-softmax over 19 channels, gather at target class, write prob.
__global__ void __launch_bounds__(256) main_pass(const float* __restrict__ pred,
                                                 const int* __restrict__ target) {
    const int stride = gridDim.x * blockDim.x;
    unsigned int vcnt = 0;

    for (int i = blockIdx.x * blockDim.x + threadIdx.x; i < N_PIX; i += stride) {
        int b = i / HWP;
        int hw = i - b * HWP;
        const float* p = pred + b * (NCLS * HWP) + hw;

        int t = target[i];
        bool valid = (t != IGNORE_LBL);
        int tc = valid ? t : 0;

        float vals[NCLS];
        float m = -1e30f;
        float vt = 0.0f;
#pragma unroll
        for (int c = 0; c < NCLS; c++) {
            float x = p[c * HWP];
            vals[c] = x;
            m = fmaxf(m, x);
            if (c == tc) vt = x;      // predicated select, no dynamic indexing
        }
        float s = 0.0f;
#pragma unroll
        for (int c = 0; c < NCLS; c++) s += __expf(vals[c] - m);

        float logp = vt - m - __logf(s);
        float pr = valid ? __expf(logp) : 1.0f;
        g_prob[i] = pr;
        vcnt += valid ? 1u : 0u;
    }

    // block-reduce vcnt
    __shared__ unsigned int sh[32];
    int lane = threadIdx.x & 31, wid = threadIdx.x >> 5;
#pragma unroll
    for (int o = 16; o; o >>= 1) vcnt += __shfl_down_sync(0xffffffffu, vcnt, o);
    if (lane == 0) sh[wid] = vcnt;
    __syncthreads();
    if (wid == 0) {
        unsigned int v = (lane < (blockDim.x >> 5)) ? sh[lane] : 0u;
#pragma unroll
        for (int o = 16; o; o >>= 1) v += __shfl_down_sync(0xffffffffu, v, o);
        if (lane == 0) atomicAdd(&g_num_valid, v);
    }
}

// ---------------------------------------------------------------------------
// One radix-select histogram round over the prob bits (digit at `shift`).
__global__ void __launch_bounds__(256) hist_pass(int shift) {
    __shared__ unsigned int sh[256];
    sh[threadIdx.x] = 0u;
    __syncthreads();

    unsigned int mask = (shift >= 24) ? 0u : (0xFFFFFFFFu << (shift + 8));
    unsigned int prefix = g_prefix;

    const float4* p4 = reinterpret_cast<const float4*>(g_prob);
    const int n4 = N_PIX / 4;
    const int stride = gridDim.x * blockDim.x;
    for (int i = blockIdx.x * blockDim.x + threadIdx.x; i < n4; i += stride) {
        float4 v = p4[i];
        unsigned int b0 = __float_as_uint(v.x);
        unsigned int b1 = __float_as_uint(v.y);
        unsigned int b2 = __float_as_uint(v.z);
        unsigned int b3 = __float_as_uint(v.w);
        if ((b0 & mask) == prefix) atomicAdd(&sh[(b0 >> shift) & 255u], 1u);
        if ((b1 & mask) == prefix) atomicAdd(&sh[(b1 >> shift) & 255u], 1u);
        if ((b2 & mask) == prefix) atomicAdd(&sh[(b2 >> shift) & 255u], 1u);
        if ((b3 & mask) == prefix) atomicAdd(&sh[(b3 >> shift) & 255u], 1u);
    }
    __syncthreads();
    unsigned int c = sh[threadIdx.x];
    if (c) atomicAdd(&g_hist[threadIdx.x], c);
}

// Scan the 256-bin histogram, extend prefix, rebase k, clear histogram.
__global__ void scan_kernel(int shift) {
    if (threadIdx.x == 0) {
        unsigned int k = g_k;
        unsigned int cum = 0;
        int d = 0;
        for (d = 0; d < 256; d++) {
            unsigned int c = g_hist[d];
            if (cum + c >= k) break;
            cum += c;
        }
        if (d == 256) d = 255;  // safety
        g_prefix |= ((unsigned int)d) << shift;
        g_k = k - cum;
    }
    __syncthreads();
    g_hist[threadIdx.x] = 0u;
}

// ---------------------------------------------------------------------------
// Final reduce: threshold known; sum -log(prob) over kept pixels.
__global__ void __launch_bounds__(256) final_pass(const int* __restrict__ target) {
    float kth = __uint_as_float(g_prefix);
    float thr = fmaxf(kth, THRESH_F);
    bool do_ohem = (g_num_valid >= MIN_KEPT_K);  // implies num_valid > 0

    const float4* p4 = reinterpret_cast<const float4*>(g_prob);
    const int4* t4 = reinterpret_cast<const int4*>(target);
    const int n4 = N_PIX / 4;
    const int stride = gridDim.x * blockDim.x;

    float lsum = 0.0f;
    unsigned int cnt = 0;
    for (int i = blockIdx.x * blockDim.x + threadIdx.x; i < n4; i += stride) {
        float4 pv = p4[i];
        int4 tv = t4[i];
        float pr[4] = {pv.x, pv.y, pv.z, pv.w};
        int tg[4] = {tv.x, tv.y, tv.z, tv.w};
#pragma unroll
        for (int j = 0; j < 4; j++) {
            bool valid = (tg[j] != IGNORE_LBL);
            bool keep = valid && (!do_ohem || pr[j] <= thr);
            if (keep) {
                lsum += -__logf(pr[j]);
                cnt++;
            }
        }
    }

    // block reductions (float sum + uint count)
    __shared__ float shf[32];
    __shared__ unsigned int shu[32];
    int lane = threadIdx.x & 31, wid = threadIdx.x >> 5;
#pragma unroll
    for (int o = 16; o; o >>= 1) {
        lsum += __shfl_down_sync(0xffffffffu, lsum, o);
        cnt += __shfl_down_sync(0xffffffffu, cnt, o);
    }
    if (lane == 0) { shf[wid] = lsum; shu[wid] = cnt; }
    __syncthreads();
    if (wid == 0) {
        float v = (lane < (blockDim.x >> 5)) ? shf[lane] : 0.0f;
        unsigned int u = (lane < (blockDim.x >> 5)) ? shu[lane] : 0u;
#pragma unroll
        for (int o = 16; o; o >>= 1) {
            v += __shfl_down_sync(0xffffffffu, v, o);
            u += __shfl_down_sync(0xffffffffu, u, o);
        }
        if (lane == 0) {
            atomicAdd(&g_sum, (double)v);
            atomicAdd(&g_cnt, u);
        }
    }
}

__global__ void finalize_kernel(float* __restrict__ out) {
    unsigned int c = g_cnt;
    if (c < 1u) c = 1u;
    out[0] = (float)(g_sum / (double)c);
}

// ---------------------------------------------------------------------------
extern "C" void kernel_launch(void* const* d_in, const int* in_sizes, int n_in,
                              void* d_out, int out_size) {
    const float* pred = (const float*)d_in[0];
    const int* target = (const int*)d_in[1];
    float* out = (float*)d_out;

    init_kernel<<<1, 256>>>();
    main_pass<<<1184, 256>>>(pred, target);

    const int shifts[4] = {24, 16, 8, 0};
    for (int r = 0; r < 4; r++) {
        hist_pass<<<592, 256>>>(shifts[r]);
        scan_kernel<<<1, 256>>>(shifts[r]);
    }

    final_pass<<<1184, 256>>>(target);
    finalize_kernel<<<1, 1>>>(out);
}

// round 2
// speedup vs baseline: 1.2475x; 1.2475x over previous
#include <cuda_runtime.h>

// Problem constants
#define BATCH 8
#define NCLS 19
#define HH 768
#define WW 768
#define HWP (HH * WW)                 // 589824
#define N_PIX (BATCH * HWP)           // 4718592
#define IGNORE_LBL 255
#define MIN_KEPT_K 262144u
#define THRESH_F 0.7f

// Scratch (no cudaMalloc allowed)
__device__ float g_prob[N_PIX];                // 18.9 MB
__device__ unsigned int g_hist16[65536];       // 256 KB
__device__ unsigned int g_hist256[256];
__device__ unsigned int g_prefix;
__device__ unsigned int g_k;
__device__ unsigned int g_num_valid;
__device__ unsigned int g_done;
__device__ double g_sum;
__device__ unsigned int g_cnt;

// ---------------------------------------------------------------------------
__global__ void init_kernel() {
    int gtid = blockIdx.x * blockDim.x + threadIdx.x;
    if (gtid < 65536) g_hist16[gtid] = 0u;
    if (gtid < 256) g_hist256[gtid] = 0u;
    if (gtid == 0) {
        g_prefix = 0u;
        g_k = MIN_KEPT_K;   // k = min(N, MIN_KEPT) = MIN_KEPT since N > MIN_KEPT
        g_num_valid = 0u;
        g_done = 0u;
        g_sum = 0.0;
        g_cnt = 0u;
    }
}

// ---------------------------------------------------------------------------
// Main pass: log-softmax over 19 channels, gather at target class, write prob,
// and build the radix round-1 histogram (top 8 bits) with warp aggregation.
__global__ void __launch_bounds__(256) main_pass(const float* __restrict__ pred,
                                                 const int* __restrict__ target) {
    __shared__ unsigned int shh[256];
    if (threadIdx.x < 256) shh[threadIdx.x] = 0u;
    __syncthreads();

    const int stride = gridDim.x * blockDim.x;
    unsigned int vcnt = 0;

    for (int i = blockIdx.x * blockDim.x + threadIdx.x; i < N_PIX; i += stride) {
        int b = i / HWP;
        int hw = i - b * HWP;
        const float* p = pred + b * (NCLS * HWP) + hw;

        int t = target[i];
        bool valid = (t != IGNORE_LBL);
        int tc = valid ? t : 0;

        float vals[NCLS];
        float m = -1e30f;
        float vt = 0.0f;
#pragma unroll
        for (int c = 0; c < NCLS; c++) {
            float x = p[c * HWP];
            vals[c] = x;
            m = fmaxf(m, x);
            if (c == tc) vt = x;      // predicated select, no dynamic indexing
        }
        float s = 0.0f;
#pragma unroll
        for (int c = 0; c < NCLS; c++) s += __expf(vals[c] - m);

        float logp = vt - m - __logf(s);
        float pr = valid ? __expf(logp) : 1.0f;
        g_prob[i] = pr;
        vcnt += valid ? 1u : 0u;

        // warp-aggregated shared hist (probs cluster into few exponent bins)
        unsigned int bin = __float_as_uint(pr) >> 24;
        unsigned int am = __activemask();
        unsigned int mmask = __match_any_sync(am, bin);
        int leader = __ffs(mmask) - 1;
        if ((int)(threadIdx.x & 31) == leader)
            atomicAdd(&shh[bin], (unsigned int)__popc(mmask));
    }

    // block-reduce vcnt
    __shared__ unsigned int sh[32];
    int lane = threadIdx.x & 31, wid = threadIdx.x >> 5;
#pragma unroll
    for (int o = 16; o; o >>= 1) vcnt += __shfl_down_sync(0xffffffffu, vcnt, o);
    if (lane == 0) sh[wid] = vcnt;
    __syncthreads();
    if (wid == 0) {
        unsigned int v = (lane < (blockDim.x >> 5)) ? sh[lane] : 0u;
#pragma unroll
        for (int o = 16; o; o >>= 1) v += __shfl_down_sync(0xffffffffu, v, o);
        if (lane == 0) atomicAdd(&g_num_valid, v);
    }

    // merge shared hist
    unsigned int c = shh[threadIdx.x];
    if (c) atomicAdd(&g_hist256[threadIdx.x], c);
}

// ---------------------------------------------------------------------------
// Parallel 256-bin scan: find digit containing rank k, extend prefix, rebase k.
// Clears the histogram afterwards (hist256 is reused for round 3).
__global__ void scan256_kernel(int shift) {
    __shared__ unsigned int s[256];
    int t = threadIdx.x;
    unsigned int c = g_hist256[t];
    s[t] = c;
    __syncthreads();
#pragma unroll
    for (int o = 1; o < 256; o <<= 1) {
        unsigned int v = (t >= o) ? s[t - o] : 0u;
        __syncthreads();
        s[t] += v;
        __syncthreads();
    }
    unsigned int k = g_k;
    unsigned int incl = s[t];
    unsigned int excl = incl - c;
    if (excl < k && k <= incl) {
        atomicOr(&g_prefix, ((unsigned int)t) << shift);
        g_k = k - excl;
    }
    g_hist256[t] = 0u;
}

// ---------------------------------------------------------------------------
// Round 2: 16-bit histogram (bits 23..8) of elements matching the top-8 prefix.
__global__ void __launch_bounds__(256) hist16_pass() {
    unsigned int prefix = g_prefix;   // top 8 bits set
    const float4* p4 = reinterpret_cast<const float4*>(g_prob);
    const int n4 = N_PIX / 4;
    const int stride = gridDim.x * blockDim.x;
    for (int i = blockIdx.x * blockDim.x + threadIdx.x; i < n4; i += stride) {
        float4 v = p4[i];
        unsigned int b0 = __float_as_uint(v.x);
        unsigned int b1 = __float_as_uint(v.y);
        unsigned int b2 = __float_as_uint(v.z);
        unsigned int b3 = __float_as_uint(v.w);
        if ((b0 & 0xFF000000u) == prefix) atomicAdd(&g_hist16[(b0 >> 8) & 0xFFFFu], 1u);
        if ((b1 & 0xFF000000u) == prefix) atomicAdd(&g_hist16[(b1 >> 8) & 0xFFFFu], 1u);
        if ((b2 & 0xFF000000u) == prefix) atomicAdd(&g_hist16[(b2 >> 8) & 0xFFFFu], 1u);
        if ((b3 & 0xFF000000u) == prefix) atomicAdd(&g_hist16[(b3 >> 8) & 0xFFFFu], 1u);
    }
}

// Parallel scan of 65536 bins with 1024 threads (64 bins/thread).
__global__ void __launch_bounds__(1024) scan16_kernel() {
    __shared__ unsigned int s[1024];
    int t = threadIdx.x;
    int base = t * 64;

    unsigned int lsum = 0;
    const uint4* h4 = reinterpret_cast<const uint4*>(g_hist16);
#pragma unroll
    for (int j = 0; j < 16; j++) {
        uint4 u = h4[(base >> 2) + j];
        lsum += u.x + u.y + u.z + u.w;
    }
    s[t] = lsum;
    __syncthreads();
#pragma unroll
    for (int o = 1; o < 1024; o <<= 1) {
        unsigned int v = (t >= o) ? s[t - o] : 0u;
        __syncthreads();
        s[t] += v;
        __syncthreads();
    }
    unsigned int k = g_k;
    unsigned int incl = s[t];
    unsigned int excl = incl - lsum;
    if (excl < k && k <= incl) {
        unsigned int cum = excl;
        for (int b = 0; b < 64; b++) {
            unsigned int c = g_hist16[base + b];
            cum += c;
            if (cum >= k) {
                atomicOr(&g_prefix, ((unsigned int)(base + b)) << 8);
                g_k = k - (cum - c);
                break;
            }
        }
    }
}

// Round 3: low 8-bit histogram of elements matching the top-24 prefix.
__global__ void __launch_bounds__(256) hist8_pass() {
    __shared__ unsigned int shh[256];
    shh[threadIdx.x] = 0u;
    __syncthreads();

    unsigned int prefix = g_prefix;   // top 24 bits set
    const float4* p4 = reinterpret_cast<const float4*>(g_prob);
    const int n4 = N_PIX / 4;
    const int stride = gridDim.x * blockDim.x;
    for (int i = blockIdx.x * blockDim.x + threadIdx.x; i < n4; i += stride) {
        float4 v = p4[i];
        unsigned int b0 = __float_as_uint(v.x);
        unsigned int b1 = __float_as_uint(v.y);
        unsigned int b2 = __float_as_uint(v.z);
        unsigned int b3 = __float_as_uint(v.w);
        if ((b0 & 0xFFFFFF00u) == prefix) atomicAdd(&shh[b0 & 255u], 1u);
        if ((b1 & 0xFFFFFF00u) == prefix) atomicAdd(&shh[b1 & 255u], 1u);
        if ((b2 & 0xFFFFFF00u) == prefix) atomicAdd(&shh[b2 & 255u], 1u);
        if ((b3 & 0xFFFFFF00u) == prefix) atomicAdd(&shh[b3 & 255u], 1u);
    }
    __syncthreads();
    unsigned int c = shh[threadIdx.x];
    if (c) atomicAdd(&g_hist256[threadIdx.x], c);
}

// ---------------------------------------------------------------------------
// Final reduce: threshold known; sum -log(prob) over kept pixels. Last block
// writes the output (fused finalize).
__global__ void __launch_bounds__(256) final_pass(const int* __restrict__ target,
                                                  float* __restrict__ out) {
    float kth = __uint_as_float(g_prefix);
    float thr = fmaxf(kth, THRESH_F);
    bool do_ohem = (g_num_valid >= MIN_KEPT_K);  // implies num_valid > 0

    const float4* p4 = reinterpret_cast<const float4*>(g_prob);
    const int4* t4 = reinterpret_cast<const int4*>(target);
    const int n4 = N_PIX / 4;
    const int stride = gridDim.x * blockDim.x;

    float lsum = 0.0f;
    unsigned int cnt = 0;
    for (int i = blockIdx.x * blockDim.x + threadIdx.x; i < n4; i += stride) {
        float4 pv = p4[i];
        int4 tv = t4[i];
        float pr[4] = {pv.x, pv.y, pv.z, pv.w};
        int tg[4] = {tv.x, tv.y, tv.z, tv.w};
#pragma unroll
        for (int j = 0; j < 4; j++) {
            bool valid = (tg[j] != IGNORE_LBL);
            bool keep = valid && (!do_ohem || pr[j] <= thr);
            if (keep) {
                lsum += -__logf(pr[j]);
                cnt++;
            }
        }
    }

    // block reductions (float sum + uint count)
    __shared__ float shf[32];
    __shared__ unsigned int shu[32];
    int lane = threadIdx.x & 31, wid = threadIdx.x >> 5;
#pragma unroll
    for (int o = 16; o; o >>= 1) {
        lsum += __shfl_down_sync(0xffffffffu, lsum, o);
        cnt += __shfl_down_sync(0xffffffffu, cnt, o);
    }
    if (lane == 0) { shf[wid] = lsum; shu[wid] = cnt; }
    __syncthreads();

    __shared__ bool is_last;
    if (threadIdx.x == 0) is_last = false;
    __syncthreads();

    if (wid == 0) {
        float v = (lane < (blockDim.x >> 5)) ? shf[lane] : 0.0f;
        unsigned int u = (lane < (blockDim.x >> 5)) ? shu[lane] : 0u;
#pragma unroll
        for (int o = 16; o; o >>= 1) {
            v += __shfl_down_sync(0xffffffffu, v, o);
            u += __shfl_down_sync(0xffffffffu, u, o);
        }
        if (lane == 0) {
            atomicAdd(&g_sum, (double)v);
            atomicAdd(&g_cnt, u);
            __threadfence();
            unsigned int done = atomicAdd(&g_done, 1u);
            if (done == gridDim.x - 1) is_last = true;
        }
    }
    __syncthreads();
    if (is_last && threadIdx.x == 0) {
        unsigned int c = g_cnt;
        if (c < 1u) c = 1u;
        out[0] = (float)(g_sum / (double)c);
    }
}

// ---------------------------------------------------------------------------
extern "C" void kernel_launch(void* const* d_in, const int* in_sizes, int n_in,
                              void* d_out, int out_size) {
    const float* pred = (const float*)d_in[0];
    const int* target = (const int*)d_in[1];
    float* out = (float*)d_out;

    init_kernel<<<64, 1024>>>();
    main_pass<<<1184, 256>>>(pred, target);      // fused round-1 hist (bits 31..24)
    scan256_kernel<<<1, 256>>>(24);
    hist16_pass<<<592, 256>>>();                 // bits 23..8
    scan16_kernel<<<1, 1024>>>();
    hist8_pass<<<592, 256>>>();                  // bits 7..0
    scan256_kernel<<<1, 256>>>(0);
    final_pass<<<1184, 256>>>(target, out);
}